// round 14
// baseline (speedup 1.0000x reference)
#include <cuda_runtime.h>
#include <math.h>
#include <stdint.h>

// ---------------------------------------------------------------- constants
#define B_ROWS   1024
#define NFEAT    256
#define NSAMP    100000
#define INV_TEMP 20.0f
#define LOG2E    1.4426950408889634f
#define LN2      0.6931471805599453f
#define XSCALE   (INV_TEMP * LOG2E)      // logits computed in base-2 domain
#define CUT      40.0f                   // 2^-40 * 1e5 ~ 1e-7 relative: safe skip

#define TILE_N    128                    // samples per tile
#define TILES_TOT 782                    // ceil(100000/128)
#define NCHUNK    18
#define TPC       44                     // ceil(782/18)
#define M_CTA     128
#define NROWT     8                      // 1024/128
#define THREADS   128                    // 4 warps, one per SMSP

// smem: A[128][260] fp32 + THREE swizzled B k-quarter buffers [128][64] fp32
#define A_STRIDE   260
#define A_FLOATS   (M_CTA * A_STRIDE)                  // 33280
#define BQ_FLOATS  (TILE_N * 64)                       // 8192 (stride 64, XOR swizzle)
#define NBUF       3
#define SMEM_TOTAL ((A_FLOATS + NBUF * BQ_FLOATS) * 4) // 231424 bytes <= 232448

// ---------------------------------------------------------------- scratch
__device__ float2 g_partials[B_ROWS * NCHUNK * 2];   // (m2, s2) per (row, chunk, n-half)
__device__ float  g_nll[B_ROWS];

// ---------------------------------------------------------------- helpers
__device__ __forceinline__ uint32_t f2tf32(float x) {
    uint32_t r; asm("cvt.rna.tf32.f32 %0, %1;" : "=r"(r) : "f"(x)); return r;
}
__device__ __forceinline__ uint32_t u2tf32(uint32_t x) {
    uint32_t r; asm("cvt.rna.tf32.f32 %0, %1;" : "=r"(r) : "r"(x)); return r;
}
__device__ __forceinline__ float ex2(float x) {
    float r; asm("ex2.approx.f32 %0, %1;" : "=f"(r) : "f"(x)); return r;
}
__device__ __forceinline__ uint32_t smem_u32(const void* p) {
    uint32_t a;
    asm("{ .reg .u64 t; cvta.to.shared.u64 t, %1; cvt.u32.u64 %0, t; }" : "=r"(a) : "l"(p));
    return a;
}
__device__ __forceinline__ void mma_tf32(float* c, uint32_t a0, uint32_t a1,
                                         uint32_t a2, uint32_t a3,
                                         uint32_t b0, uint32_t b1) {
    asm volatile(
        "mma.sync.aligned.m16n8k8.row.col.f32.tf32.tf32.f32 "
        "{%0,%1,%2,%3}, {%4,%5,%6,%7}, {%8,%9}, {%0,%1,%2,%3};"
        : "+f"(c[0]), "+f"(c[1]), "+f"(c[2]), "+f"(c[3])
        : "r"(a0), "r"(a1), "r"(a2), "r"(a3), "r"(b0), "r"(b1));
}
#define CP_COMMIT() asm volatile("cp.async.commit_group;" ::: "memory")
#define CP_WAIT1()  asm volatile("cp.async.wait_group 1;"  ::: "memory")
#define CP_WAIT0()  asm volatile("cp.async.wait_group 0;"  ::: "memory")

// ---------------------------------------------------------------- B k-quarter async load, XOR-swizzled
// Streams RAW fp32 features (conversion to tf32 happens in-register before mma).
// OOB rows zero-filled via src-size=0 (no memory access); address clamped.
__device__ __forceinline__ void ld_quarter(const float* __restrict__ feats,
                                           float* buf, int Q, int tid)
{
    const int gt = Q >> 2, q = Q & 3;
    const int row0 = gt * TILE_N;
    const uint32_t sbase = smem_u32(buf);
    #pragma unroll
    for (int i = 0; i < 16; i++) {
        int c   = i * THREADS + tid;            // float4 slot 0..2047
        int rr  = c >> 4;                       // row 0..127 (16 float4 per row)
        int cc4 = c & 15;
        int grow  = row0 + rr;
        int valid = (grow < NSAMP);
        int rowc  = valid ? grow : (NSAMP - 1);
        uint32_t sz = valid ? 16u : 0u;
        uint32_t sw = (uint32_t)(rr * 64 + ((cc4 * 4) ^ ((rr & 7) << 2)));
        const float* ga = feats + (size_t)rowc * NFEAT + q * 64 + cc4 * 4;
        asm volatile("cp.async.cg.shared.global [%0], [%1], 16, %2;"
                     :: "r"(sbase + sw * 4u), "l"(ga), "r"(sz) : "memory");
    }
}

// ---------------------------------------------------------------- main fused kernel
__global__ __launch_bounds__(THREADS, 1)
void k_main(const float* __restrict__ inputs, const float* __restrict__ feats)
{
    extern __shared__ float sm[];
    float* As  = sm;                        // [128][260]
    float* Bqs = sm + A_FLOATS;             // 3 x [128*64] swizzled quarter buffers

    const int tid = threadIdx.x;
    const int wid = tid >> 5;
    const int ln  = tid & 31;
    const int wm  = wid >> 1;               // m-half: rows wm*64 .. +63
    const int wn  = wid & 1;                // n-half: cols wn*64 .. +63
    const int lg  = ln >> 2;                // mma groupID 0..7
    const int lt  = ln & 3;                 // mma tid-in-group 0..3

    const int r0  = blockIdx.x * M_CTA;
    const int gt0 = blockIdx.y * TPC;
    int T = TILES_TOT - gt0; if (T > TPC) T = TPC;
    const int H  = 4 * T;                   // quarters
    const int Q0 = gt0 * 4;                 // absolute first quarter

    // ---- prologue: 2 quarters in flight
    ld_quarter(feats, Bqs + 0 * BQ_FLOATS, Q0 + 0, tid); CP_COMMIT();
    ld_quarter(feats, Bqs + 1 * BQ_FLOATS, Q0 + 1, tid); CP_COMMIT();

    // ---- load A: inputs * XSCALE, tf32 .rna, plain padded layout (conflict-free)
    {
        const float4* in4 = (const float4*)inputs;
        for (int i = tid; i < M_CTA * 64; i += THREADS) {
            int rr = i >> 6, cc = i & 63;
            float4 v = in4[(size_t)(r0 + rr) * 64 + cc];
            uint32_t* dst = (uint32_t*)(As + rr * A_STRIDE + cc * 4);
            dst[0] = f2tf32(v.x * XSCALE);
            dst[1] = f2tf32(v.y * XSCALE);
            dst[2] = f2tf32(v.z * XSCALE);
            dst[3] = f2tf32(v.w * XSCALE);
        }
    }

    float acc[4][8][4];
    #pragma unroll
    for (int mf = 0; mf < 4; mf++)
        #pragma unroll
        for (int nf = 0; nf < 8; nf++)
            #pragma unroll
            for (int j = 0; j < 4; j++) acc[mf][nf][j] = 0.0f;

    float m[8], s[8];   // row slot r = mf*2+hh -> row wm*64 + mf*16 + hh*8 + lg
    #pragma unroll
    for (int r = 0; r < 8; r++) { m[r] = -3.0e38f; s[r] = 0.0f; }

    const uint32_t* Ap = (const uint32_t*)As;
    const uint32_t* Aw = Ap + (wm * 64 + lg) * A_STRIDE + lt;   // + q*64 + ks*8 (+4)
    const uint32_t swz = (uint32_t)(lg << 2);
    int buf = 0;                            // h % 3

    for (int h = 0; h < H; h++) {
        if (h + 1 < H) { CP_WAIT1(); } else { CP_WAIT0(); }   // quarter h resident
        __syncthreads();                     // all warps done with quarter h-1

        if (h + 2 < H) {                     // refill buffer consumed at h-1
            int nb = buf + 2; if (nb >= NBUF) nb -= NBUF;
            ld_quarter(feats, Bqs + nb * BQ_FLOATS, Q0 + h + 2, tid);
            CP_COMMIT();
        }

        const uint32_t* Bw = (const uint32_t*)(Bqs + buf * BQ_FLOATS)
                             + (wn * 64 + lg) * 64 + lt;
        const int q = h & 3;
        const uint32_t* Aq = Aw + q * 64;

        #pragma unroll
        for (int ks = 0; ks < 8; ks++) {
            // ---- load ALL operands for this k-step first (scheduler freedom)
            uint32_t a[4][4];
            #pragma unroll
            for (int mf = 0; mf < 4; mf++) {
                const uint32_t* Am = Aq + mf * 16 * A_STRIDE + ks * 8;
                a[mf][0] = Am[0];
                a[mf][1] = Am[8 * A_STRIDE];
                a[mf][2] = Am[4];
                a[mf][3] = Am[8 * A_STRIDE + 4];
            }
            const int k0 = (ks * 8)     ^ (int)swz;   // lt already folded into Bw
            const int k1 = (ks * 8 + 4) ^ (int)swz;
            uint32_t b[8][2];
            #pragma unroll
            for (int nf = 0; nf < 8; nf++) {
                b[nf][0] = u2tf32(Bw[nf * 512 + k0]);  // .rna in-register
                b[nf][1] = u2tf32(Bw[nf * 512 + k1]);
            }
            // ---- 32 MMAs
            #pragma unroll
            for (int nf = 0; nf < 8; nf++)
                #pragma unroll
                for (int mf = 0; mf < 4; mf++)
                    mma_tf32(acc[mf][nf], a[mf][0], a[mf][1], a[mf][2], a[mf][3],
                             b[nf][0], b[nf][1]);
        }

        buf++; if (buf >= NBUF) buf = 0;

        if (q == 3) {
            // ---- tile epilogue: threshold-gated online logsumexp (base-2)
            #pragma unroll
            for (int mf = 0; mf < 4; mf++) {
                #pragma unroll
                for (int hh = 0; hh < 2; hh++) {
                    const int r = mf * 2 + hh;
                    float t0 = fmaxf(acc[mf][0][2*hh], acc[mf][0][2*hh+1]);
                    float t1 = fmaxf(acc[mf][1][2*hh], acc[mf][1][2*hh+1]);
                    float t2 = fmaxf(acc[mf][2][2*hh], acc[mf][2][2*hh+1]);
                    float t3 = fmaxf(acc[mf][3][2*hh], acc[mf][3][2*hh+1]);
                    float t4 = fmaxf(acc[mf][4][2*hh], acc[mf][4][2*hh+1]);
                    float t5 = fmaxf(acc[mf][5][2*hh], acc[mf][5][2*hh+1]);
                    float t6 = fmaxf(acc[mf][6][2*hh], acc[mf][6][2*hh+1]);
                    float t7 = fmaxf(acc[mf][7][2*hh], acc[mf][7][2*hh+1]);
                    float tmax = fmaxf(fmaxf(fmaxf(t0, t1), fmaxf(t2, t3)),
                                       fmaxf(fmaxf(t4, t5), fmaxf(t6, t7)));
                    if (tmax > m[r] - CUT) {        // rare slow path
                        float nm = fmaxf(m[r], tmax);
                        float add = 0.0f;
                        #pragma unroll
                        for (int nf = 0; nf < 8; nf++) {
                            add += ex2(acc[mf][nf][2*hh]   - nm);
                            add += ex2(acc[mf][nf][2*hh+1] - nm);
                        }
                        s[r] = s[r] * ex2(m[r] - nm) + add;
                        m[r] = nm;
                    }
                }
            }
            #pragma unroll
            for (int mf = 0; mf < 4; mf++)
                #pragma unroll
                for (int nf = 0; nf < 8; nf++)
                    #pragma unroll
                    for (int j = 0; j < 4; j++) acc[mf][nf][j] = 0.0f;
        }
    }

    // ---- merge (m,s) across the 4 lanes (lt) sharing each row; store per n-half
    #pragma unroll
    for (int r = 0; r < 8; r++) {
        float mm = m[r], ss = s[r];
        #pragma unroll
        for (int off = 1; off <= 2; off <<= 1) {
            float om = __shfl_xor_sync(0xffffffffu, mm, off);
            float os = __shfl_xor_sync(0xffffffffu, ss, off);
            float nm = fmaxf(mm, om);
            ss = ss * ex2(mm - nm) + os * ex2(om - nm);
            mm = nm;
        }
        if (lt == 0) {
            const int row = r0 + wm * 64 + (r >> 1) * 16 + (r & 1) * 8 + lg;
            g_partials[((size_t)row * NCHUNK + blockIdx.y) * 2 + wn] = make_float2(mm, ss);
        }
    }
}

// ---------------------------------------------------------------- combine + mean
__global__ void k_combine(const float* __restrict__ inputs,
                          const float* __restrict__ feats,
                          const int* __restrict__ targets)
{
    const int row = blockIdx.x;
    const int t   = threadIdx.x;

    float m = -3.0e38f, s = 0.0f;                  // base-2
    for (int c = t; c < NCHUNK * 2; c += 32) {
        float2 p = g_partials[(size_t)row * NCHUNK * 2 + c];
        float nm = fmaxf(m, p.x);
        s = s * ex2(m - nm) + p.y * ex2(p.x - nm);
        m = nm;
    }
    #pragma unroll
    for (int off = 16; off >= 1; off >>= 1) {
        float om = __shfl_xor_sync(0xffffffffu, m, off);
        float os = __shfl_xor_sync(0xffffffffu, s, off);
        float nm = fmaxf(m, om);
        s = s * ex2(m - nm) + os * ex2(om - nm);
        m = nm;
    }

    // exact target logit in fp32
    int tg = targets[row];
    tg = (tg < 0) ? 0 : ((tg >= NSAMP) ? (NSAMP - 1) : tg);
    const float* ir = inputs + (size_t)row * NFEAT;
    const float* fr = feats  + (size_t)tg  * NFEAT;
    float d = 0.0f;
    for (int k = t; k < NFEAT; k += 32) d = fmaf(ir[k], fr[k], d);
    #pragma unroll
    for (int off = 16; off >= 1; off >>= 1)
        d += __shfl_xor_sync(0xffffffffu, d, off);

    if (t == 0)
        g_nll[row] = LN2 * (m + log2f(s)) - d * INV_TEMP;
}

__global__ void k_mean(float* __restrict__ out)
{
    __shared__ float red[256];
    const int t = threadIdx.x;
    float a = 0.0f;
    for (int i = t; i < B_ROWS; i += 256) a += g_nll[i];
    red[t] = a;
    __syncthreads();
    for (int w = 128; w > 0; w >>= 1) {
        if (t < w) red[t] += red[t + w];
        __syncthreads();
    }
    if (t == 0) out[0] = red[0] * (1.0f / B_ROWS);
}

// ---------------------------------------------------------------- launch
extern "C" void kernel_launch(void* const* d_in, const int* in_sizes, int n_in,
                              void* d_out, int out_size)
{
    const float* inputs  = (const float*)d_in[0];
    const int*   targets = (const int*)d_in[1];
    const float* feats   = (const float*)d_in[2];

    cudaFuncSetAttribute(k_main, cudaFuncAttributeMaxDynamicSharedMemorySize, SMEM_TOTAL);

    dim3 grid(NROWT, NCHUNK);               // row-tile fastest -> B shared in L2
    k_main<<<grid, THREADS, SMEM_TOTAL>>>(inputs, feats);

    k_combine<<<B_ROWS, 32>>>(inputs, feats, targets);
    k_mean<<<1, 256>>>((float*)d_out);
}

// round 16
// speedup vs baseline: 1.0315x; 1.0315x over previous
#include <cuda_runtime.h>
#include <math.h>
#include <stdint.h>

// ---------------------------------------------------------------- constants
#define B_ROWS   1024
#define NFEAT    256
#define NSAMP    100000
#define INV_TEMP 20.0f
#define LOG2E    1.4426950408889634f
#define LN2      0.6931471805599453f
#define XSCALE   (INV_TEMP * LOG2E)      // logits computed in base-2 domain
#define CUT      40.0f                   // 2^-40 * 1e5 ~ 1e-7 relative: safe skip

#define TILE_N    128                    // samples per tile
#define TILES_TOT 782                    // ceil(100000/128)
#define NS_PAD    (TILES_TOT * TILE_N)   // 100096 (pad rows zeroed)
#define NCHUNK    18
#define TPC       44                     // ceil(782/18)
#define M_CTA     128
#define NROWT     8                      // 1024/128
#define THREADS   128                    // 4 warps, one per SMSP

// smem: A[128][260] fp32 + THREE swizzled B k-quarter buffers [128][64] fp32
#define A_STRIDE   260
#define A_FLOATS   (M_CTA * A_STRIDE)                  // 33280
#define BQ_FLOATS  (TILE_N * 64)                       // 8192 (stride 64, XOR swizzle)
#define NBUF       3
#define SMEM_TOTAL ((A_FLOATS + NBUF * BQ_FLOATS) * 4) // 231424 bytes <= 232448

// ---------------------------------------------------------------- scratch
__device__ float  g_ftf[(size_t)NS_PAD * NFEAT];     // tf32(.rna) features, pad rows = 0
__device__ float2 g_partials[B_ROWS * NCHUNK * 2];   // (m2, s2) per (row, chunk, n-half)
__device__ float  g_nll[B_ROWS];

// ---------------------------------------------------------------- helpers
__device__ __forceinline__ uint32_t f2tf32(float x) {
    uint32_t r; asm("cvt.rna.tf32.f32 %0, %1;" : "=r"(r) : "f"(x)); return r;
}
__device__ __forceinline__ float ex2(float x) {
    float r; asm("ex2.approx.f32 %0, %1;" : "=f"(r) : "f"(x)); return r;
}
__device__ __forceinline__ uint32_t smem_u32(const void* p) {
    uint32_t a;
    asm("{ .reg .u64 t; cvta.to.shared.u64 t, %1; cvt.u32.u64 %0, t; }" : "=r"(a) : "l"(p));
    return a;
}
__device__ __forceinline__ void mma_tf32(float* c, uint32_t a0, uint32_t a1,
                                         uint32_t a2, uint32_t a3,
                                         uint32_t b0, uint32_t b1) {
    asm volatile(
        "mma.sync.aligned.m16n8k8.row.col.f32.tf32.tf32.f32 "
        "{%0,%1,%2,%3}, {%4,%5,%6,%7}, {%8,%9}, {%0,%1,%2,%3};"
        : "+f"(c[0]), "+f"(c[1]), "+f"(c[2]), "+f"(c[3])
        : "r"(a0), "r"(a1), "r"(a2), "r"(a3), "r"(b0), "r"(b1));
}
#define CP_COMMIT() asm volatile("cp.async.commit_group;" ::: "memory")
#define CP_WAIT1()  asm volatile("cp.async.wait_group 1;"  ::: "memory")
#define CP_WAIT0()  asm volatile("cp.async.wait_group 0;"  ::: "memory")

// ---------------------------------------------------------------- convert features -> tf32 (.rna), pad rows zero
__global__ void k_convert_feats(const float* __restrict__ feats)
{
    const float4* f4 = (const float4*)feats;
    float4* o4 = (float4*)g_ftf;
    const int n4 = NS_PAD * NFEAT / 4;
    for (int i = blockIdx.x * blockDim.x + threadIdx.x; i < n4; i += gridDim.x * blockDim.x) {
        int row = i >> 6;                       // 64 float4 per row
        float4 o;
        if (row < NSAMP) {
            float4 v = f4[i];
            o.x = __uint_as_float(f2tf32(v.x));
            o.y = __uint_as_float(f2tf32(v.y));
            o.z = __uint_as_float(f2tf32(v.z));
            o.w = __uint_as_float(f2tf32(v.w));
        } else {
            o = make_float4(0.f, 0.f, 0.f, 0.f);
        }
        o4[i] = o;
    }
}

// ---------------------------------------------------------------- B k-quarter async load, XOR-swizzled
// physical float offset = row*64 + (k ^ ((row & 7) << 2)); 16B aligned, conflict-free
__device__ __forceinline__ void ld_quarter(float* buf, int Q, int tid)
{
    const int gt = Q >> 2, q = Q & 3;
    const float* src = g_ftf + (size_t)gt * TILE_N * NFEAT + q * 64;
    const uint32_t sbase = smem_u32(buf);
    #pragma unroll
    for (int i = 0; i < 16; i++) {
        int c   = i * THREADS + tid;            // float4 slot 0..2047
        int rr  = c >> 4;                       // row 0..127 (16 float4 per row)
        int cc4 = c & 15;
        uint32_t sw = (uint32_t)(rr * 64 + ((cc4 * 4) ^ ((rr & 7) << 2)));
        const float* ga = src + (size_t)rr * NFEAT + cc4 * 4;
        asm volatile("cp.async.cg.shared.global [%0], [%1], 16;"
                     :: "r"(sbase + sw * 4u), "l"(ga) : "memory");
    }
}

// operand-load macros for the software pipeline
#define LOAD_A(dst, ks) do {                                                  \
    _Pragma("unroll")                                                         \
    for (int _mf = 0; _mf < 4; _mf++) {                                       \
        const uint32_t* _Am = Aq + _mf * 16 * A_STRIDE + (ks) * 8;            \
        (dst)[_mf][0] = _Am[0];                                               \
        (dst)[_mf][1] = _Am[8 * A_STRIDE];                                    \
        (dst)[_mf][2] = _Am[4];                                               \
        (dst)[_mf][3] = _Am[8 * A_STRIDE + 4];                                \
    }                                                                         \
} while (0)

#define LOAD_B(dst, ks) do {                                                  \
    const int _k0 = ((ks) * 8)     ^ (int)swz;                                \
    const int _k1 = ((ks) * 8 + 4) ^ (int)swz;                                \
    _Pragma("unroll")                                                         \
    for (int _nf = 0; _nf < 8; _nf++) {                                       \
        (dst)[_nf][0] = Bw[_nf * 512 + _k0];                                  \
        (dst)[_nf][1] = Bw[_nf * 512 + _k1];                                  \
    }                                                                         \
} while (0)

// ---------------------------------------------------------------- main fused kernel
__global__ __launch_bounds__(THREADS, 1)
void k_main(const float* __restrict__ inputs)
{
    extern __shared__ float sm[];
    float* As  = sm;                        // [128][260]
    float* Bqs = sm + A_FLOATS;             // 3 x [128*64] swizzled quarter buffers

    const int tid = threadIdx.x;
    const int wid = tid >> 5;
    const int ln  = tid & 31;
    const int wm  = wid >> 1;               // m-half: rows wm*64 .. +63
    const int wn  = wid & 1;                // n-half: cols wn*64 .. +63
    const int lg  = ln >> 2;                // mma groupID 0..7
    const int lt  = ln & 3;                 // mma tid-in-group 0..3

    const int r0  = blockIdx.x * M_CTA;
    const int gt0 = blockIdx.y * TPC;
    int T = TILES_TOT - gt0; if (T > TPC) T = TPC;
    const int H  = 4 * T;                   // quarters
    const int Q0 = gt0 * 4;                 // absolute first quarter

    // ---- prologue: 2 quarters in flight
    ld_quarter(Bqs + 0 * BQ_FLOATS, Q0 + 0, tid); CP_COMMIT();
    ld_quarter(Bqs + 1 * BQ_FLOATS, Q0 + 1, tid); CP_COMMIT();

    // ---- load A: inputs * XSCALE, tf32 .rna, plain padded layout (conflict-free)
    {
        const float4* in4 = (const float4*)inputs;
        for (int i = tid; i < M_CTA * 64; i += THREADS) {
            int rr = i >> 6, cc = i & 63;
            float4 v = in4[(size_t)(r0 + rr) * 64 + cc];
            uint32_t* dst = (uint32_t*)(As + rr * A_STRIDE + cc * 4);
            dst[0] = f2tf32(v.x * XSCALE);
            dst[1] = f2tf32(v.y * XSCALE);
            dst[2] = f2tf32(v.z * XSCALE);
            dst[3] = f2tf32(v.w * XSCALE);
        }
    }

    float acc[4][8][4];
    #pragma unroll
    for (int mf = 0; mf < 4; mf++)
        #pragma unroll
        for (int nf = 0; nf < 8; nf++)
            #pragma unroll
            for (int j = 0; j < 4; j++) acc[mf][nf][j] = 0.0f;

    float m[8], s[8];   // row slot r = mf*2+hh -> row wm*64 + mf*16 + hh*8 + lg
    #pragma unroll
    for (int r = 0; r < 8; r++) { m[r] = -3.0e38f; s[r] = 0.0f; }

    const uint32_t* Ap = (const uint32_t*)As;
    const uint32_t* Aw = Ap + (wm * 64 + lg) * A_STRIDE + lt;   // + q*64 + ks*8 (+4)
    const uint32_t swz = (uint32_t)(lg << 2);
    int buf = 0;                            // h % 3

    for (int h = 0; h < H; h++) {
        if (h + 1 < H) { CP_WAIT1(); } else { CP_WAIT0(); }   // quarter h resident
        __syncthreads();                     // all warps done with quarter h-1

        if (h + 2 < H) {                     // refill buffer consumed at h-1
            int nb = buf + 2; if (nb >= NBUF) nb -= NBUF;
            ld_quarter(Bqs + nb * BQ_FLOATS, Q0 + h + 2, tid);
            CP_COMMIT();
        }

        const uint32_t* Bw = (const uint32_t*)(Bqs + buf * BQ_FLOATS)
                             + (wn * 64 + lg) * 64 + lt;
        const int q = h & 3;
        const uint32_t* Aq = Aw + q * 64;

        // ---- software-pipelined k-steps: loads for ks+1 issued before MMAs of ks
        uint32_t a_cur[4][4], b_cur[8][2], a_nxt[4][4], b_nxt[8][2];
        LOAD_A(a_cur, 0);
        LOAD_B(b_cur, 0);
        #pragma unroll
        for (int ks = 0; ks < 8; ks++) {
            if (ks < 7) {
                LOAD_A(a_nxt, ks + 1);
                LOAD_B(b_nxt, ks + 1);
            }
            #pragma unroll
            for (int nf = 0; nf < 8; nf++)
                #pragma unroll
                for (int mf = 0; mf < 4; mf++)
                    mma_tf32(acc[mf][nf], a_cur[mf][0], a_cur[mf][1],
                             a_cur[mf][2], a_cur[mf][3], b_cur[nf][0], b_cur[nf][1]);
            if (ks < 7) {
                #pragma unroll
                for (int mf = 0; mf < 4; mf++)
                    #pragma unroll
                    for (int j = 0; j < 4; j++) a_cur[mf][j] = a_nxt[mf][j];
                #pragma unroll
                for (int nf = 0; nf < 8; nf++) {
                    b_cur[nf][0] = b_nxt[nf][0];
                    b_cur[nf][1] = b_nxt[nf][1];
                }
            }
        }

        buf++; if (buf >= NBUF) buf = 0;

        if (q == 3) {
            // ---- tile epilogue: threshold-gated online logsumexp (base-2)
            #pragma unroll
            for (int mf = 0; mf < 4; mf++) {
                #pragma unroll
                for (int hh = 0; hh < 2; hh++) {
                    const int r = mf * 2 + hh;
                    float t0 = fmaxf(acc[mf][0][2*hh], acc[mf][0][2*hh+1]);
                    float t1 = fmaxf(acc[mf][1][2*hh], acc[mf][1][2*hh+1]);
                    float t2 = fmaxf(acc[mf][2][2*hh], acc[mf][2][2*hh+1]);
                    float t3 = fmaxf(acc[mf][3][2*hh], acc[mf][3][2*hh+1]);
                    float t4 = fmaxf(acc[mf][4][2*hh], acc[mf][4][2*hh+1]);
                    float t5 = fmaxf(acc[mf][5][2*hh], acc[mf][5][2*hh+1]);
                    float t6 = fmaxf(acc[mf][6][2*hh], acc[mf][6][2*hh+1]);
                    float t7 = fmaxf(acc[mf][7][2*hh], acc[mf][7][2*hh+1]);
                    float tmax = fmaxf(fmaxf(fmaxf(t0, t1), fmaxf(t2, t3)),
                                       fmaxf(fmaxf(t4, t5), fmaxf(t6, t7)));
                    if (tmax > m[r] - CUT) {        // rare slow path
                        float nm = fmaxf(m[r], tmax);
                        float add = 0.0f;
                        #pragma unroll
                        for (int nf = 0; nf < 8; nf++) {
                            add += ex2(acc[mf][nf][2*hh]   - nm);
                            add += ex2(acc[mf][nf][2*hh+1] - nm);
                        }
                        s[r] = s[r] * ex2(m[r] - nm) + add;
                        m[r] = nm;
                    }
                }
            }
            #pragma unroll
            for (int mf = 0; mf < 4; mf++)
                #pragma unroll
                for (int nf = 0; nf < 8; nf++)
                    #pragma unroll
                    for (int j = 0; j < 4; j++) acc[mf][nf][j] = 0.0f;
        }
    }

    // ---- merge (m,s) across the 4 lanes (lt) sharing each row; store per n-half
    #pragma unroll
    for (int r = 0; r < 8; r++) {
        float mm = m[r], ss = s[r];
        #pragma unroll
        for (int off = 1; off <= 2; off <<= 1) {
            float om = __shfl_xor_sync(0xffffffffu, mm, off);
            float os = __shfl_xor_sync(0xffffffffu, ss, off);
            float nm = fmaxf(mm, om);
            ss = ss * ex2(mm - nm) + os * ex2(om - nm);
            mm = nm;
        }
        if (lt == 0) {
            const int row = r0 + wm * 64 + (r >> 1) * 16 + (r & 1) * 8 + lg;
            g_partials[((size_t)row * NCHUNK + blockIdx.y) * 2 + wn] = make_float2(mm, ss);
        }
    }
}

// ---------------------------------------------------------------- combine + mean
__global__ void k_combine(const float* __restrict__ inputs,
                          const float* __restrict__ feats,
                          const int* __restrict__ targets)
{
    const int row = blockIdx.x;
    const int t   = threadIdx.x;

    float m = -3.0e38f, s = 0.0f;                  // base-2
    for (int c = t; c < NCHUNK * 2; c += 32) {
        float2 p = g_partials[(size_t)row * NCHUNK * 2 + c];
        float nm = fmaxf(m, p.x);
        s = s * ex2(m - nm) + p.y * ex2(p.x - nm);
        m = nm;
    }
    #pragma unroll
    for (int off = 16; off >= 1; off >>= 1) {
        float om = __shfl_xor_sync(0xffffffffu, m, off);
        float os = __shfl_xor_sync(0xffffffffu, s, off);
        float nm = fmaxf(m, om);
        s = s * ex2(m - nm) + os * ex2(om - nm);
        m = nm;
    }

    // exact target logit in fp32
    int tg = targets[row];
    tg = (tg < 0) ? 0 : ((tg >= NSAMP) ? (NSAMP - 1) : tg);
    const float* ir = inputs + (size_t)row * NFEAT;
    const float* fr = feats  + (size_t)tg  * NFEAT;
    float d = 0.0f;
    for (int k = t; k < NFEAT; k += 32) d = fmaf(ir[k], fr[k], d);
    #pragma unroll
    for (int off = 16; off >= 1; off >>= 1)
        d += __shfl_xor_sync(0xffffffffu, d, off);

    if (t == 0)
        g_nll[row] = LN2 * (m + log2f(s)) - d * INV_TEMP;
}

__global__ void k_mean(float* __restrict__ out)
{
    __shared__ float red[256];
    const int t = threadIdx.x;
    float a = 0.0f;
    for (int i = t; i < B_ROWS; i += 256) a += g_nll[i];
    red[t] = a;
    __syncthreads();
    for (int w = 128; w > 0; w >>= 1) {
        if (t < w) red[t] += red[t + w];
        __syncthreads();
    }
    if (t == 0) out[0] = red[0] * (1.0f / B_ROWS);
}

// ---------------------------------------------------------------- launch
extern "C" void kernel_launch(void* const* d_in, const int* in_sizes, int n_in,
                              void* d_out, int out_size)
{
    const float* inputs  = (const float*)d_in[0];
    const int*   targets = (const int*)d_in[1];
    const float* feats   = (const float*)d_in[2];

    cudaFuncSetAttribute(k_main, cudaFuncAttributeMaxDynamicSharedMemorySize, SMEM_TOTAL);

    k_convert_feats<<<2048, 256>>>(feats);

    dim3 grid(NROWT, NCHUNK);               // row-tile fastest -> B shared in L2
    k_main<<<grid, THREADS, SMEM_TOTAL>>>(inputs);

    k_combine<<<B_ROWS, 32>>>(inputs, feats, targets);
    k_mean<<<1, 256>>>((float*)d_out);
}

// round 17
// speedup vs baseline: 1.0841x; 1.0511x over previous
#include <cuda_runtime.h>
#include <math.h>
#include <stdint.h>

// ---------------------------------------------------------------- constants
#define B_ROWS   1024
#define NFEAT    256
#define NSAMP    100000
#define INV_TEMP 20.0f
#define LOG2E    1.4426950408889634f
#define LN2      0.6931471805599453f
#define XSCALE   (INV_TEMP * LOG2E)      // logits computed in base-2 domain
#define CUT      40.0f                   // 2^-40 * 1e5 ~ 1e-7 relative: safe skip

#define TILE_N    128                    // samples per tile
#define TILES_TOT 782                    // ceil(100000/128)
#define NS_PAD    (TILES_TOT * TILE_N)   // 100096 (pad rows zeroed)
#define NCHUNK    18
#define TPC       44                     // ceil(782/18)
#define M_CTA     64
#define NROWT     16                     // 1024/64
#define THREADS   128                    // 4 warps, one per SMSP

// smem: A[64][256] fp32 XOR-swizzled + THREE B k-eighth buffers [128][32] swizzled
#define A_FLOATS   (M_CTA * 256)                       // 16384
#define BE_FLOATS  (TILE_N * 32)                       // 4096
#define NBUF       3
#define SMEM_TOTAL ((A_FLOATS + NBUF * BE_FLOATS) * 4) // 114688 -> 2 CTAs/SM

// ---------------------------------------------------------------- scratch
__device__ float  g_ftf[(size_t)NS_PAD * NFEAT];     // tf32(.rna) features, pad rows = 0
__device__ float2 g_partials[B_ROWS * NCHUNK * 2];   // (m2, s2) per (row, chunk, n-half)
__device__ float  g_nll[B_ROWS];

// ---------------------------------------------------------------- helpers
__device__ __forceinline__ uint32_t f2tf32(float x) {
    uint32_t r; asm("cvt.rna.tf32.f32 %0, %1;" : "=r"(r) : "f"(x)); return r;
}
__device__ __forceinline__ float ex2(float x) {
    float r; asm("ex2.approx.f32 %0, %1;" : "=f"(r) : "f"(x)); return r;
}
__device__ __forceinline__ uint32_t smem_u32(const void* p) {
    uint32_t a;
    asm("{ .reg .u64 t; cvta.to.shared.u64 t, %1; cvt.u32.u64 %0, t; }" : "=r"(a) : "l"(p));
    return a;
}
__device__ __forceinline__ void mma_tf32(float* c, uint32_t a0, uint32_t a1,
                                         uint32_t a2, uint32_t a3,
                                         uint32_t b0, uint32_t b1) {
    asm volatile(
        "mma.sync.aligned.m16n8k8.row.col.f32.tf32.tf32.f32 "
        "{%0,%1,%2,%3}, {%4,%5,%6,%7}, {%8,%9}, {%0,%1,%2,%3};"
        : "+f"(c[0]), "+f"(c[1]), "+f"(c[2]), "+f"(c[3])
        : "r"(a0), "r"(a1), "r"(a2), "r"(a3), "r"(b0), "r"(b1));
}
#define CP_COMMIT() asm volatile("cp.async.commit_group;" ::: "memory")
#define CP_WAIT1()  asm volatile("cp.async.wait_group 1;"  ::: "memory")
#define CP_WAIT0()  asm volatile("cp.async.wait_group 0;"  ::: "memory")

// ---------------------------------------------------------------- convert features -> tf32 (.rna), pad rows zero
__global__ void k_convert_feats(const float* __restrict__ feats)
{
    const float4* f4 = (const float4*)feats;
    float4* o4 = (float4*)g_ftf;
    const int n4 = NS_PAD * NFEAT / 4;
    for (int i = blockIdx.x * blockDim.x + threadIdx.x; i < n4; i += gridDim.x * blockDim.x) {
        int row = i >> 6;                       // 64 float4 per row
        float4 o;
        if (row < NSAMP) {
            float4 v = f4[i];
            o.x = __uint_as_float(f2tf32(v.x));
            o.y = __uint_as_float(f2tf32(v.y));
            o.z = __uint_as_float(f2tf32(v.z));
            o.w = __uint_as_float(f2tf32(v.w));
        } else {
            o = make_float4(0.f, 0.f, 0.f, 0.f);
        }
        o4[i] = o;
    }
}

// ---------------------------------------------------------------- B k-eighth async load, XOR-swizzled
// physical float offset = row*32 + (c ^ ((row & 7) << 2)); 16B aligned, conflict-free
__device__ __forceinline__ void ld_eighth(float* buf, int E, int tid)
{
    const int gt = E >> 3, e = E & 7;
    const float* src = g_ftf + (size_t)gt * TILE_N * NFEAT + e * 32;
    const uint32_t sbase = smem_u32(buf);
    #pragma unroll
    for (int i = 0; i < 8; i++) {
        int c   = i * THREADS + tid;            // float4 slot 0..1023
        int rr  = c >> 3;                       // row 0..127 (8 float4 per row)
        int cc4 = c & 7;
        uint32_t sw = (uint32_t)(rr * 32 + ((cc4 * 4) ^ ((rr & 7) << 2)));
        const float* ga = src + (size_t)rr * NFEAT + cc4 * 4;
        asm volatile("cp.async.cg.shared.global [%0], [%1], 16;"
                     :: "r"(sbase + sw * 4u), "l"(ga) : "memory");
    }
}

// ---------------------------------------------------------------- main fused kernel
__global__ __launch_bounds__(THREADS, 2)
void k_main(const float* __restrict__ inputs)
{
    extern __shared__ float sm[];
    float* As  = sm;                        // [64][256] XOR-swizzled
    float* Bes = sm + A_FLOATS;             // 3 x [128*32] swizzled eighth buffers

    const int tid = threadIdx.x;
    const int wid = tid >> 5;
    const int ln  = tid & 31;
    const int wm  = wid >> 1;               // m-half: rows wm*32 .. +31
    const int wn  = wid & 1;                // n-half: cols wn*64 .. +63
    const int lg  = ln >> 2;                // mma groupID 0..7
    const int lt  = ln & 3;                 // mma tid-in-group 0..3

    const int r0  = blockIdx.x * M_CTA;
    const int gt0 = blockIdx.y * TPC;
    int T = TILES_TOT - gt0; if (T > TPC) T = TPC;
    const int H  = 8 * T;                   // eighths
    const int E0 = gt0 * 8;                 // absolute first eighth

    // ---- prologue: 2 eighths in flight
    ld_eighth(Bes + 0 * BE_FLOATS, E0 + 0, tid); CP_COMMIT();
    ld_eighth(Bes + 1 * BE_FLOATS, E0 + 1, tid); CP_COMMIT();

    // ---- load A: inputs * XSCALE, tf32 .rna, XOR-swizzled [64][256]
    {
        const float4* in4 = (const float4*)inputs;
        for (int i = tid; i < M_CTA * 64; i += THREADS) {
            int rr = i >> 6, cc = i & 63;
            float4 v = in4[(size_t)(r0 + rr) * 64 + cc];
            uint32_t off = (uint32_t)(rr * 256 + ((cc * 4) ^ ((rr & 7) << 2)));
            uint32_t* dst = (uint32_t*)(As + off);
            dst[0] = f2tf32(v.x * XSCALE);
            dst[1] = f2tf32(v.y * XSCALE);
            dst[2] = f2tf32(v.z * XSCALE);
            dst[3] = f2tf32(v.w * XSCALE);
        }
    }

    float acc[2][8][4];
    #pragma unroll
    for (int mf = 0; mf < 2; mf++)
        #pragma unroll
        for (int nf = 0; nf < 8; nf++)
            #pragma unroll
            for (int j = 0; j < 4; j++) acc[mf][nf][j] = 0.0f;

    float m[4], s[4];   // row slot r = mf*2+hh -> row wm*32 + mf*16 + hh*8 + lg
    #pragma unroll
    for (int r = 0; r < 4; r++) { m[r] = -3.0e38f; s[r] = 0.0f; }

    const uint32_t* Ap = (const uint32_t*)As;
    const uint32_t* Aw = Ap + (wm * 32 + lg) * 256;     // + swizzled k col
    const int swz = (int)(lg << 2);
    int buf = 0;                            // h % 3

    for (int h = 0; h < H; h++) {
        if (h + 1 < H) { CP_WAIT1(); } else { CP_WAIT0(); }   // eighth h resident
        __syncthreads();                     // all warps done with eighth h-1

        if (h + 2 < H) {                     // refill buffer consumed at h-1
            int nb = buf + 2; if (nb >= NBUF) nb -= NBUF;
            ld_eighth(Bes + nb * BE_FLOATS, E0 + h + 2, tid);
            CP_COMMIT();
        }

        const uint32_t* Bw = (const uint32_t*)(Bes + buf * BE_FLOATS)
                             + (wn * 64 + lg) * 32;
        const int e = h & 7;

        #pragma unroll
        for (int ks = 0; ks < 4; ks++) {
            const int kc0 = ((ks * 8 + lt)     ^ swz);       // bank-distinct
            const int kc1 = ((ks * 8 + lt + 4) ^ swz);
            const int ac0 = e * 32 + kc0;
            const int ac1 = e * 32 + kc1;
            uint32_t a[2][4];
            #pragma unroll
            for (int mf = 0; mf < 2; mf++) {
                const uint32_t* Am = Aw + mf * 16 * 256;
                a[mf][0] = Am[ac0];
                a[mf][1] = Am[8 * 256 + ac0];
                a[mf][2] = Am[ac1];
                a[mf][3] = Am[8 * 256 + ac1];
            }
            #pragma unroll
            for (int nf = 0; nf < 8; nf++) {
                uint32_t b0 = Bw[nf * 256 + kc0];   // nf*8 rows * 32 floats
                uint32_t b1 = Bw[nf * 256 + kc1];
                mma_tf32(acc[0][nf], a[0][0], a[0][1], a[0][2], a[0][3], b0, b1);
                mma_tf32(acc[1][nf], a[1][0], a[1][1], a[1][2], a[1][3], b0, b1);
            }
        }

        buf++; if (buf >= NBUF) buf = 0;

        if (e == 7) {
            // ---- tile epilogue: threshold-gated online logsumexp (base-2)
            #pragma unroll
            for (int mf = 0; mf < 2; mf++) {
                #pragma unroll
                for (int hh = 0; hh < 2; hh++) {
                    const int r = mf * 2 + hh;
                    float t0 = fmaxf(acc[mf][0][2*hh], acc[mf][0][2*hh+1]);
                    float t1 = fmaxf(acc[mf][1][2*hh], acc[mf][1][2*hh+1]);
                    float t2 = fmaxf(acc[mf][2][2*hh], acc[mf][2][2*hh+1]);
                    float t3 = fmaxf(acc[mf][3][2*hh], acc[mf][3][2*hh+1]);
                    float t4 = fmaxf(acc[mf][4][2*hh], acc[mf][4][2*hh+1]);
                    float t5 = fmaxf(acc[mf][5][2*hh], acc[mf][5][2*hh+1]);
                    float t6 = fmaxf(acc[mf][6][2*hh], acc[mf][6][2*hh+1]);
                    float t7 = fmaxf(acc[mf][7][2*hh], acc[mf][7][2*hh+1]);
                    float tmax = fmaxf(fmaxf(fmaxf(t0, t1), fmaxf(t2, t3)),
                                       fmaxf(fmaxf(t4, t5), fmaxf(t6, t7)));
                    if (tmax > m[r] - CUT) {        // rare slow path
                        float nm = fmaxf(m[r], tmax);
                        float add = 0.0f;
                        #pragma unroll
                        for (int nf = 0; nf < 8; nf++) {
                            add += ex2(acc[mf][nf][2*hh]   - nm);
                            add += ex2(acc[mf][nf][2*hh+1] - nm);
                        }
                        s[r] = s[r] * ex2(m[r] - nm) + add;
                        m[r] = nm;
                    }
                }
            }
            #pragma unroll
            for (int mf = 0; mf < 2; mf++)
                #pragma unroll
                for (int nf = 0; nf < 8; nf++)
                    #pragma unroll
                    for (int j = 0; j < 4; j++) acc[mf][nf][j] = 0.0f;
        }
    }

    // ---- merge (m,s) across the 4 lanes (lt) sharing each row; store per n-half
    #pragma unroll
    for (int r = 0; r < 4; r++) {
        float mm = m[r], ss = s[r];
        #pragma unroll
        for (int off = 1; off <= 2; off <<= 1) {
            float om = __shfl_xor_sync(0xffffffffu, mm, off);
            float os = __shfl_xor_sync(0xffffffffu, ss, off);
            float nm = fmaxf(mm, om);
            ss = ss * ex2(mm - nm) + os * ex2(om - nm);
            mm = nm;
        }
        if (lt == 0) {
            const int row = r0 + wm * 32 + (r >> 1) * 16 + (r & 1) * 8 + lg;
            g_partials[((size_t)row * NCHUNK + blockIdx.y) * 2 + wn] = make_float2(mm, ss);
        }
    }
}

// ---------------------------------------------------------------- combine + mean
__global__ void k_combine(const float* __restrict__ inputs,
                          const float* __restrict__ feats,
                          const int* __restrict__ targets)
{
    const int row = blockIdx.x;
    const int t   = threadIdx.x;

    float m = -3.0e38f, s = 0.0f;                  // base-2
    for (int c = t; c < NCHUNK * 2; c += 32) {
        float2 p = g_partials[(size_t)row * NCHUNK * 2 + c];
        float nm = fmaxf(m, p.x);
        s = s * ex2(m - nm) + p.y * ex2(p.x - nm);
        m = nm;
    }
    #pragma unroll
    for (int off = 16; off >= 1; off >>= 1) {
        float om = __shfl_xor_sync(0xffffffffu, m, off);
        float os = __shfl_xor_sync(0xffffffffu, s, off);
        float nm = fmaxf(m, om);
        s = s * ex2(m - nm) + os * ex2(om - nm);
        m = nm;
    }

    // exact target logit in fp32
    int tg = targets[row];
    tg = (tg < 0) ? 0 : ((tg >= NSAMP) ? (NSAMP - 1) : tg);
    const float* ir = inputs + (size_t)row * NFEAT;
    const float* fr = feats  + (size_t)tg  * NFEAT;
    float d = 0.0f;
    for (int k = t; k < NFEAT; k += 32) d = fmaf(ir[k], fr[k], d);
    #pragma unroll
    for (int off = 16; off >= 1; off >>= 1)
        d += __shfl_xor_sync(0xffffffffu, d, off);

    if (t == 0)
        g_nll[row] = LN2 * (m + log2f(s)) - d * INV_TEMP;
}

__global__ void k_mean(float* __restrict__ out)
{
    __shared__ float red[256];
    const int t = threadIdx.x;
    float a = 0.0f;
    for (int i = t; i < B_ROWS; i += 256) a += g_nll[i];
    red[t] = a;
    __syncthreads();
    for (int w = 128; w > 0; w >>= 1) {
        if (t < w) red[t] += red[t + w];
        __syncthreads();
    }
    if (t == 0) out[0] = red[0] * (1.0f / B_ROWS);
}

// ---------------------------------------------------------------- launch
extern "C" void kernel_launch(void* const* d_in, const int* in_sizes, int n_in,
                              void* d_out, int out_size)
{
    const float* inputs  = (const float*)d_in[0];
    const int*   targets = (const int*)d_in[1];
    const float* feats   = (const float*)d_in[2];

    cudaFuncSetAttribute(k_main, cudaFuncAttributeMaxDynamicSharedMemorySize, SMEM_TOTAL);

    k_convert_feats<<<2048, 256>>>(feats);

    dim3 grid(NROWT, NCHUNK);               // row-tile fastest -> B shared in L2
    k_main<<<grid, THREADS, SMEM_TOTAL>>>(inputs);

    k_combine<<<B_ROWS, 32>>>(inputs, feats, targets);
    k_mean<<<1, 256>>>((float*)d_out);
}